// round 10
// baseline (speedup 1.0000x reference)
#include <cuda_runtime.h>
#include <cstdint>

#define T_STEPS 1024
#define BATCH   64
#define DIN     256
#define DH      256
#define G4      1024   // 4*DH
#define OUT_MAIN (T_STEPS*BATCH*DH)

// ---------------- scratch (static device globals; no allocation) ----------------
__device__ float g_Gx[(size_t)T_STEPS * BATCH * G4];   // precomputed x-part of gates
__device__ float g_WxT[DIN * G4];                      // Wx transposed [k][j]
__device__ float g_bvec[G4];                           // packed bias

// ---------------- primitives ----------------
__device__ __forceinline__ uint32_t sh_u32(const void* p) {
    return (uint32_t)__cvta_generic_to_shared(p);
}
__device__ __forceinline__ uint32_t mapa_sh(uint32_t addr, uint32_t rank) {
    uint32_t r;
    asm("mapa.shared::cluster.u32 %0, %1, %2;" : "=r"(r) : "r"(addr), "r"(rank));
    return r;
}
__device__ __forceinline__ void st_cluster_f32(uint32_t addr, float v) {
    asm volatile("st.shared::cluster.b32 [%0], %1;" :: "r"(addr), "r"(__float_as_uint(v)) : "memory");
}
__device__ __forceinline__ void st_release_cluster_u32(uint32_t addr, uint32_t v) {
    asm volatile("st.release.cluster.shared::cluster.b32 [%0], %1;" :: "r"(addr), "r"(v) : "memory");
}
__device__ __forceinline__ uint32_t ld_acquire_cluster_sh(uint32_t addr) {
    uint32_t v;
    asm volatile("ld.acquire.cluster.shared::cta.b32 %0, [%1];" : "=r"(v) : "r"(addr) : "memory");
    return v;
}
__device__ __forceinline__ uint32_t to_tf32(float f) {
    uint32_t r;
    asm("cvt.rna.tf32.f32 %0, %1;" : "=r"(r) : "f"(f));
    return r;
}
__device__ __forceinline__ void mma_tf32(float& d0, float& d1, float& d2, float& d3,
                                         uint32_t a0, uint32_t a1, uint32_t a2, uint32_t a3,
                                         uint32_t b0, uint32_t b1) {
    asm volatile("mma.sync.aligned.m16n8k8.row.col.f32.tf32.tf32.f32 "
                 "{%0,%1,%2,%3}, {%4,%5,%6,%7}, {%8,%9}, {%0,%1,%2,%3};"
                 : "+f"(d0), "+f"(d1), "+f"(d2), "+f"(d3)
                 : "r"(a0), "r"(a1), "r"(a2), "r"(a3), "r"(b0), "r"(b1));
}
__device__ __forceinline__ float sigm(float x) { return 1.f / (1.f + __expf(-x)); }
__device__ __forceinline__ float tanh_fast(float x) {
    float e = __expf(2.f * x);
    return (e - 1.f) * __frcp_rn(e + 1.f);
}

// ---------------- prep: pack Wx (k-major) + bias ----------------
__global__ void prep_kernel(const float* __restrict__ Wf, const float* __restrict__ Wi,
                            const float* __restrict__ Wg, const float* __restrict__ Wo,
                            const float* __restrict__ bF, const float* __restrict__ bI,
                            const float* __restrict__ bG, const float* __restrict__ bO)
{
    int idx = blockIdx.x * blockDim.x + threadIdx.x;
    const float* Ws[4] = {Wf, Wi, Wg, Wo};
    for (int i = idx; i < DIN * G4; i += gridDim.x * blockDim.x) {
        int k = i >> 10;
        int j = i & (G4 - 1);
        int gate = j >> 8;
        int row  = j & 255;
        g_WxT[i] = Ws[gate][row * 512 + k];
    }
    if (idx < G4) {
        int gate = idx >> 8, row = idx & 255;
        const float* bs[4] = {bF, bI, bG, bO};
        g_bvec[idx] = bs[gate][row];
    }
}

// ---------------- phase 1: Gx = X @ Wx^T + b   (65536 x 1024 x 256 SGEMM) ----------------
__global__ __launch_bounds__(256) void gemm_x_kernel(const float* __restrict__ A)
{
    __shared__ float As[8][128];
    __shared__ float Bs[8][128];

    int tid = threadIdx.x;
    int bn = blockIdx.x;
    int bm = blockIdx.y;
    int tx = tid & 15;
    int ty = tid >> 4;

    float acc[8][8];
    #pragma unroll
    for (int i = 0; i < 8; i++)
        #pragma unroll
        for (int j = 0; j < 8; j++) acc[i][j] = 0.f;

    const float* Aptr = A + (size_t)bm * 128 * DIN;
    const float* Bptr = g_WxT + bn * 128;

    int arow = tid >> 1;
    int acol = (tid & 1) << 2;
    int bkk  = tid >> 5;
    int bj   = (tid & 31) << 2;

    for (int k0 = 0; k0 < DIN; k0 += 8) {
        float4 a4 = *(const float4*)(Aptr + arow * DIN + k0 + acol);
        As[acol + 0][arow] = a4.x;
        As[acol + 1][arow] = a4.y;
        As[acol + 2][arow] = a4.z;
        As[acol + 3][arow] = a4.w;
        *(float4*)&Bs[bkk][bj] = *(const float4*)(Bptr + (size_t)(k0 + bkk) * G4 + bj);
        __syncthreads();

        #pragma unroll
        for (int kk = 0; kk < 8; kk++) {
            float4 a0 = *(const float4*)&As[kk][ty * 8];
            float4 a1 = *(const float4*)&As[kk][ty * 8 + 4];
            float4 b0 = *(const float4*)&Bs[kk][tx * 8];
            float4 b1 = *(const float4*)&Bs[kk][tx * 8 + 4];
            float af[8] = {a0.x, a0.y, a0.z, a0.w, a1.x, a1.y, a1.z, a1.w};
            float bf[8] = {b0.x, b0.y, b0.z, b0.w, b1.x, b1.y, b1.z, b1.w};
            #pragma unroll
            for (int mi = 0; mi < 8; mi++)
                #pragma unroll
                for (int ni = 0; ni < 8; ni++)
                    acc[mi][ni] += af[mi] * bf[ni];
        }
        __syncthreads();
    }

    int jbase = bn * 128 + tx * 8;
    float4 bb0 = *(const float4*)&g_bvec[jbase];
    float4 bb1 = *(const float4*)&g_bvec[jbase + 4];
    #pragma unroll
    for (int mi = 0; mi < 8; mi++) {
        size_t r = (size_t)bm * 128 + ty * 8 + mi;
        float* op = g_Gx + r * G4 + jbase;
        float4 o0 = make_float4(acc[mi][0] + bb0.x, acc[mi][1] + bb0.y,
                                acc[mi][2] + bb0.z, acc[mi][3] + bb0.w);
        float4 o1 = make_float4(acc[mi][4] + bb1.x, acc[mi][5] + bb1.y,
                                acc[mi][6] + bb1.z, acc[mi][7] + bb1.w);
        *(float4*)op = o0;
        *(float4*)(op + 4) = o1;
    }
}

// ---------------- phase 2: persistent recurrent kernel (tf32 MMA + DSMEM exchange) ----------------
// 16 clusters (batch groups of 4) x 8 CTAs (32 h cols x 4 gates = 128 gate rows each).
// Weights resident as tf32 A-fragments. h lives ONLY in smem: owners push h(t+1) into
// all 8 ranks' double-buffered hT via st.shared::cluster; per-producer flag words in
// consumer smem (st.release.cluster after bar) -> consumers poll LOCAL smem.
__global__ __launch_bounds__(256, 1) __cluster_dims__(8, 1, 1)
void lstm_kernel(const float* __restrict__ Wf, const float* __restrict__ Wi,
                 const float* __restrict__ Wg, const float* __restrict__ Wo,
                 const float* __restrict__ h0, const float* __restrict__ c0,
                 float* __restrict__ out, int out_size)
{
    __shared__ alignas(16) float hT_sm[2][DH * 4];   // [buf][k*4 + batch], tf32-rounded
    __shared__ float D_sm[128][9];                   // gates [gate_row][batch], padded
    __shared__ alignas(16) unsigned int flag_sm[8];  // one word per producer rank

    int tid  = threadIdx.x;
    int lane = tid & 31;
    int mt   = tid >> 5;          // warp = m-tile 0..7
    int grp  = blockIdx.x >> 3;   // batch group 0..15
    int cg   = blockIdx.x & 7;    // cluster rank / h-slice 0..7

    // ---- load A fragments (weights, tf32) once ----
    int row_off = lane >> 2;            // 0..7
    int colk    = lane & 3;
    int g_th    = row_off & 3;
    const float* Wsel = (g_th == 0) ? Wf : (g_th == 1) ? Wi : (g_th == 2) ? Wg : Wo;
    int hh0 = mt * 4 + (row_off >> 2);
    int hh1 = hh0 + 2;
    const float* p0 = Wsel + (cg * 32 + hh0) * 512 + 256;
    const float* p1 = Wsel + (cg * 32 + hh1) * 512 + 256;

    uint32_t wA[32][4];
    #pragma unroll
    for (int kt = 0; kt < 32; kt++) {
        int k0 = kt * 8;
        wA[kt][0] = to_tf32(p0[k0 + colk]);
        wA[kt][1] = to_tf32(p1[k0 + colk]);
        wA[kt][2] = to_tf32(p0[k0 + colk + 4]);
        wA[kt][3] = to_tf32(p1[k0 + colk + 4]);
    }

    // ---- cell ownership: tid<128, batch = tid&3, h col = tid>>2 ----
    int bloc  = tid & 3;
    int hh    = tid >> 2;
    int bglob = grp * 4 + bloc;
    int hglob = cg * 32 + hh;
    float cval = (tid < 128) ? c0[bglob * DH + hglob] : 0.f;

    // ---- init smem: hT buffer 0 from h0, flags = 0 ----
    #pragma unroll
    for (int j = 0; j < 4; j++) {
        int i = tid + 256 * j;            // i = k*4 + b
        int k = i >> 2, bb = i & 3;
        hT_sm[0][i] = __uint_as_float(to_tf32(h0[(grp * 4 + bb) * DH + k]));
    }
    if (tid < 8) flag_sm[tid] = 0;
    __syncthreads();
    asm volatile("barrier.cluster.arrive.aligned;" ::: "memory");
    asm volatile("barrier.cluster.wait.aligned;" ::: "memory");

    // ---- precompute peer addresses ----
    uint32_t hT_base   = sh_u32(hT_sm);
    uint32_t flag_base = sh_u32(flag_sm);
    uint32_t elem_off  = (uint32_t)(hglob * 4 + bloc) * 4u;   // within a buffer
    uint32_t peer_hT[8];
    #pragma unroll
    for (int r = 0; r < 8; r++) peer_hT[r] = mapa_sh(hT_base, r) + elem_off;
    uint32_t my_flag   = flag_base + (uint32_t)(tid < 8 ? tid : 0) * 4u;           // local poll addr
    uint32_t peer_flag = (tid < 8) ? (mapa_sh(flag_base, tid) + (uint32_t)cg * 4u) : 0u;

    // ---- B-fragment smem index ----
    int bcol  = lane >> 2;
    bool bval = bcol < 4;
    int bidx  = (lane & 3) * 4 + (bval ? bcol : 0);

    #pragma unroll 1
    for (int t = 0; t < T_STEPS; t++) {
        // prefetch Gx for this step (hides DRAM latency behind the wait)
        float gx0, gx1, gx2, gx3;
        if (tid < 128) {
            const float* gp = g_Gx + (size_t)t * (BATCH * G4) + (size_t)bglob * G4 + hglob;
            gx0 = __ldcs(gp);
            gx1 = __ldcs(gp + 256);
            gx2 = __ldcs(gp + 512);
            gx3 = __ldcs(gp + 768);
        }

        // wait: poll LOCAL smem flags until every producer has published h[t]
        if (tid < 8) {
            while (ld_acquire_cluster_sh(my_flag) < (unsigned)t) { }
        }
        __syncthreads();

        // tensor MMA: D[16 gate rows x 4 batches] per warp, k=256 in 32 chained steps
        float d0 = 0.f, d1 = 0.f, d2 = 0.f, d3 = 0.f;
        const float* hTf = hT_sm[t & 1];
        #pragma unroll
        for (int kt = 0; kt < 32; kt++) {
            uint32_t b0 = 0u, b1 = 0u;
            if (bval) {
                b0 = __float_as_uint(hTf[kt * 32 + bidx]);
                b1 = __float_as_uint(hTf[kt * 32 + 16 + bidx]);
            }
            mma_tf32(d0, d1, d2, d3, wA[kt][0], wA[kt][1], wA[kt][2], wA[kt][3], b0, b1);
        }

        // write D cols 0..3 (batches) to smem
        int r0 = mt * 16 + (lane >> 2);
        int cc = lane & 3;
        if (cc < 2) {
            D_sm[r0][2 * cc]         = d0;
            D_sm[r0][2 * cc + 1]     = d1;
            D_sm[r0 + 8][2 * cc]     = d2;
            D_sm[r0 + 8][2 * cc + 1] = d3;
        }
        __syncthreads();

        // cell update + DSMEM push of h(t+1) into all 8 ranks' other buffer
        if (tid < 128) {
            float fg = sigm(D_sm[hh * 4 + 0][bloc] + gx0);
            float ig = sigm(D_sm[hh * 4 + 1][bloc] + gx1);
            float gg = tanh_fast(D_sm[hh * 4 + 2][bloc] + gx2);
            float og = sigm(D_sm[hh * 4 + 3][bloc] + gx3);
            cval = fg * cval + ig * gg;
            float hn = og * tanh_fast(cval);

            float hn_tf = __uint_as_float(to_tf32(hn));
            uint32_t boff = (uint32_t)((t + 1) & 1) * (DH * 4 * 4);   // buffer byte offset
            #pragma unroll
            for (int r = 0; r < 8; r++) st_cluster_f32(peer_hT[r] + boff, hn_tf);

            int idx = bglob * DH + hglob;
            out[(size_t)t * (BATCH * DH) + idx] = hn;
            if (t == T_STEPS - 1 && out_size > OUT_MAIN) {
                out[(size_t)OUT_MAIN + idx] = hn;
                out[(size_t)OUT_MAIN + BATCH * DH + idx] = cval;
            }
        }
        __syncthreads();   // all owners' remote stores issued before the release below

        // publish: one release store into each peer's flag word for this rank
        if (tid < 8) st_release_cluster_u32(peer_flag, (unsigned)(t + 1));
    }

    // no CTA may exit while peers' stores targeting its smem are in flight
    asm volatile("barrier.cluster.arrive.aligned;" ::: "memory");
    asm volatile("barrier.cluster.wait.aligned;" ::: "memory");
}

// ---------------- launch ----------------
extern "C" void kernel_launch(void* const* d_in, const int* in_sizes, int n_in,
                              void* d_out, int out_size)
{
    const float* inputs = (const float*)d_in[0];
    const float* h0     = (const float*)d_in[1];
    const float* c0     = (const float*)d_in[2];
    const float* Wf     = (const float*)d_in[3];
    const float* bF     = (const float*)d_in[4];
    const float* Wi     = (const float*)d_in[5];
    const float* bI     = (const float*)d_in[6];
    const float* Wg     = (const float*)d_in[7];
    const float* bG     = (const float*)d_in[8];
    const float* Wo     = (const float*)d_in[9];
    const float* bO     = (const float*)d_in[10];
    float* out = (float*)d_out;

    prep_kernel<<<256, 256>>>(Wf, Wi, Wg, Wo, bF, bI, bG, bO);
    gemm_x_kernel<<<dim3(8, 512), 256>>>(inputs);
    lstm_kernel<<<128, 256>>>(Wf, Wi, Wg, Wo, h0, c0, out, out_size);
}